// round 1
// baseline (speedup 1.0000x reference)
#include <cuda_runtime.h>
#include <cuda_bf16.h>
#include <stdint.h>

// ---------------- problem constants ----------------
#define QS      1204
#define FD      7
#define ROWLEN  (QS*FD)        // 8428 floats per batch row
#define ROW4    (ROWLEN/4)     // 2107 float4 per row (8428 % 4 == 0)
#define BATCH   16384
#define FK      600            // feature dim after maxpool
#define FKP     640            // padded to multiple of 64 (zeros)

// smem strides (padded for bank-conflict-free fragment loads)
#define S1ST    72             // stage-1 tiles: 64 + 8 pad (bf16)
#define S2ST    136            // stage-2 tiles: 128 + 8 pad (bf16)
#define F1ST    133            // fp32 h1: 128 + 5 pad
#define REGB    34816          // 128*136*2 bytes, one smem region
#define SMEM_BYTES (6*REGB)    // 208896 B dynamic smem for mlp kernel

// scratch: feat pre-split into bf16 hi/lo, rows padded to 640 (cols 600..639 = 0)
__device__ __align__(16) __nv_bfloat16 g_feat_hi[(size_t)BATCH*FKP];
__device__ __align__(16) __nv_bfloat16 g_feat_lo[(size_t)BATCH*FKP];

// ---------------- helpers ----------------
__device__ __forceinline__ uint32_t pack_bf2(__nv_bfloat16 e0, __nv_bfloat16 e1) {
    // element e0 -> low half, e1 -> high half (little-endian)
    return ((uint32_t)__bfloat16_as_ushort(e1) << 16) | (uint32_t)__bfloat16_as_ushort(e0);
}

__device__ __forceinline__ void split_bf16(float v, __nv_bfloat16& hi, __nv_bfloat16& lo) {
    hi = __float2bfloat16(v);
    lo = __float2bfloat16(v - __bfloat162float(hi));
}

__device__ __forceinline__ uint32_t lds32(const __nv_bfloat16* p) {
    return *(const uint32_t*)p;
}

__device__ __forceinline__ void mma16816(float* c,
    uint32_t a0, uint32_t a1, uint32_t a2, uint32_t a3,
    uint32_t b0, uint32_t b1)
{
    asm volatile(
        "mma.sync.aligned.m16n8k16.row.col.f32.bf16.bf16.f32 "
        "{%0,%1,%2,%3}, {%4,%5,%6,%7}, {%8,%9}, {%0,%1,%2,%3};\n"
        : "+f"(c[0]), "+f"(c[1]), "+f"(c[2]), "+f"(c[3])
        : "r"(a0), "r"(a1), "r"(a2), "r"(a3), "r"(b0), "r"(b1));
}

// ---------------- kernel 1: x -> feat (hi/lo bf16) ----------------
// one block per batch row; stream 8428 floats through smem, project 7->1,
// sliding maxpool 5 offsets x 120 blocks -> 600 features, split to bf16 hi/lo.
__global__ __launch_bounds__(256) void feat_kernel(
    const float* __restrict__ x,
    const float* __restrict__ w_step,
    const float* __restrict__ b_step)
{
    __shared__ float sx[ROWLEN];
    __shared__ float ss[QS];

    const int row = blockIdx.x;
    const int tid = threadIdx.x;

    // coalesced float4 stream into smem
    const float4* src = (const float4*)(x + (size_t)row * ROWLEN);
    float4* dst = (float4*)sx;
    #pragma unroll 4
    for (int i = tid; i < ROW4; i += 256) dst[i] = src[i];

    const float w0 = __ldg(w_step + 0), w1 = __ldg(w_step + 1), w2 = __ldg(w_step + 2),
                w3 = __ldg(w_step + 3), w4 = __ldg(w_step + 4), w5 = __ldg(w_step + 5),
                w6 = __ldg(w_step + 6), bs = __ldg(b_step);
    __syncthreads();

    // s[q] = x[q,:] . w_step + b_step  (stride-7 smem reads: 7 coprime 32 -> conflict-free)
    for (int q = tid; q < QS; q += 256) {
        const float* p = sx + q * FD;
        float v = fmaf(p[0], w0, fmaf(p[1], w1, fmaf(p[2], w2,
                  fmaf(p[3], w3, fmaf(p[4], w4, fmaf(p[5], w5, p[6] * w6))))));
        ss[q] = v + bs;
    }
    __syncthreads();

    __nv_bfloat16* fh = g_feat_hi + (size_t)row * FKP;
    __nv_bfloat16* fl = g_feat_lo + (size_t)row * FKP;

    // feat[j], j = block*5 + off: max over ss[off + block*10 .. +10)
    for (int t = tid; t < FKP / 2; t += 256) {
        const int j0 = 2 * t;
        float v0 = 0.f, v1 = 0.f;
        if (j0 < FK) {
            {
                const int bl = j0 / 5, off = j0 % 5;
                const float* p = ss + off + bl * 10;
                float m = p[0];
                #pragma unroll
                for (int i = 1; i < 10; ++i) m = fmaxf(m, p[i]);
                v0 = m;
            }
            {
                const int j1 = j0 + 1;
                const int bl = j1 / 5, off = j1 % 5;
                const float* p = ss + off + bl * 10;
                float m = p[0];
                #pragma unroll
                for (int i = 1; i < 10; ++i) m = fmaxf(m, p[i]);
                v1 = m;
            }
        }
        __nv_bfloat16 h0, l0, h1, l1;
        split_bf16(v0, h0, l0);
        split_bf16(v1, h1, l1);
        *(uint32_t*)(fh + j0) = pack_bf2(h0, h1);
        *(uint32_t*)(fl + j0) = pack_bf2(l0, l1);
    }
}

// ---------------- split-bf16 MMA inner loop ----------------
// A: [m][k] row-major bf16 (hi/lo), stride AST; B: [n][k] bf16 (hi/lo), stride BST
// each warp: 32(M) x 64(N) tile = 2 m-tiles x 8 n-tiles of m16n8k16
template<int AST, int BST>
__device__ __forceinline__ void gemm_step(
    const __nv_bfloat16* __restrict__ Ah, const __nv_bfloat16* __restrict__ Al,
    const __nv_bfloat16* __restrict__ Bh, const __nv_bfloat16* __restrict__ Bl,
    int ksteps, float (&acc)[2][8][4], int mb, int nb, int g, int tg)
{
    for (int kk = 0; kk < ksteps; ++kk) {
        const int k0 = kk * 16 + 2 * tg;
        uint32_t ah[2][4], al[2][4];
        #pragma unroll
        for (int mt = 0; mt < 2; ++mt) {
            const __nv_bfloat16* pa = Ah + (mb + mt * 16 + g) * AST + k0;
            ah[mt][0] = lds32(pa);
            ah[mt][1] = lds32(pa + 8 * AST);
            ah[mt][2] = lds32(pa + 8);
            ah[mt][3] = lds32(pa + 8 * AST + 8);
            const __nv_bfloat16* pl = Al + (mb + mt * 16 + g) * AST + k0;
            al[mt][0] = lds32(pl);
            al[mt][1] = lds32(pl + 8 * AST);
            al[mt][2] = lds32(pl + 8);
            al[mt][3] = lds32(pl + 8 * AST + 8);
        }
        #pragma unroll
        for (int nt = 0; nt < 8; ++nt) {
            const __nv_bfloat16* pb = Bh + (nb + nt * 8 + g) * BST + k0;
            const uint32_t bh0 = lds32(pb), bh1 = lds32(pb + 8);
            const __nv_bfloat16* pq = Bl + (nb + nt * 8 + g) * BST + k0;
            const uint32_t bl0 = lds32(pq), bl1 = lds32(pq + 8);
            #pragma unroll
            for (int mt = 0; mt < 2; ++mt) {
                mma16816(acc[mt][nt], ah[mt][0], ah[mt][1], ah[mt][2], ah[mt][3], bh0, bh1);
                mma16816(acc[mt][nt], ah[mt][0], ah[mt][1], ah[mt][2], ah[mt][3], bl0, bl1);
                mma16816(acc[mt][nt], al[mt][0], al[mt][1], al[mt][2], al[mt][3], bh0, bh1);
            }
        }
    }
}

__device__ __forceinline__ void store_split_pair(
    __nv_bfloat16* H, __nv_bfloat16* L, int m, int col, float v0, float v1)
{
    __nv_bfloat16 h0, l0, h1, l1;
    split_bf16(v0, h0, l0);
    split_bf16(v1, h1, l1);
    *(uint32_t*)(H + m * S2ST + col) = pack_bf2(h0, h1);
    *(uint32_t*)(L + m * S2ST + col) = pack_bf2(l0, l1);
}

// ---------------- kernel 2: feat -> logits (entire MLP) ----------------
// one block = 128 batch rows, 256 threads (8 warps: warpM = wid&3, warpN = wid>>2)
__global__ __launch_bounds__(256) void mlp_kernel(
    const float* __restrict__ wA, const float* __restrict__ bA,
    const float* __restrict__ w1, const float* __restrict__ b1,
    const float* __restrict__ w2, const float* __restrict__ b2,
    const float* __restrict__ wB, const float* __restrict__ bB,
    const float* __restrict__ wC, const float* __restrict__ bC,
    float* __restrict__ out)
{
    extern __shared__ char smem[];
    __nv_bfloat16* R0 = (__nv_bfloat16*)(smem + 0 * REGB);
    __nv_bfloat16* R1 = (__nv_bfloat16*)(smem + 1 * REGB);
    __nv_bfloat16* R2 = (__nv_bfloat16*)(smem + 2 * REGB);
    __nv_bfloat16* R3 = (__nv_bfloat16*)(smem + 3 * REGB);
    __nv_bfloat16* R4 = (__nv_bfloat16*)(smem + 4 * REGB);
    __nv_bfloat16* R5 = (__nv_bfloat16*)(smem + 5 * REGB);

    const int tid  = threadIdx.x;
    const int wid  = tid >> 5;
    const int lane = tid & 31;
    const int g    = lane >> 2;
    const int tg   = lane & 3;
    const int mb   = (wid & 3) * 32;
    const int nb   = (wid >> 2) * 64;
    const int row0 = blockIdx.x * 128;

    float acc[2][8][4];
    #pragma unroll
    for (int a = 0; a < 2; ++a)
        #pragma unroll
        for (int b = 0; b < 8; ++b)
            #pragma unroll
            for (int c = 0; c < 4; ++c) acc[a][b][c] = 0.f;

    // ======== Stage 1: h0 = relu(feat @ wA^T + bA), K = 640 (padded) ========
    {
        __nv_bfloat16* sAh = R0;  // [128][72]
        __nv_bfloat16* sAl = R1;
        __nv_bfloat16* sBh = R2;  // [n=128][k=72]
        __nv_bfloat16* sBl = R3;
        const __nv_bfloat16* fh = g_feat_hi + (size_t)row0 * FKP;
        const __nv_bfloat16* fl = g_feat_lo + (size_t)row0 * FKP;

        for (int c = 0; c < FKP / 64; ++c) {
            // A tile: 128 rows x 64 cols bf16 (already split), uint4 copies
            #pragma unroll 4
            for (int i = tid; i < 1024; i += 256) {
                const int m = i >> 3, q = i & 7;
                *(uint4*)(sAh + m * S1ST + q * 8) = *(const uint4*)(fh + (size_t)m * FKP + c * 64 + q * 8);
                *(uint4*)(sAl + m * S1ST + q * 8) = *(const uint4*)(fl + (size_t)m * FKP + c * 64 + q * 8);
            }
            // B tile: wA[n][k] fp32 -> split bf16, [n][k] layout
            #pragma unroll 4
            for (int i = tid; i < 8192; i += 256) {
                const int n = i >> 6, kl = i & 63;
                const int k = c * 64 + kl;
                const float v = (k < FK) ? __ldg(wA + n * FK + k) : 0.f;
                __nv_bfloat16 h, l;
                split_bf16(v, h, l);
                sBh[n * S1ST + kl] = h;
                sBl[n * S1ST + kl] = l;
            }
            __syncthreads();
            gemm_step<S1ST, S1ST>(sAh, sAl, sBh, sBl, 4, acc, mb, nb, g, tg);
            __syncthreads();
        }
    }

    // epilogue 1: h0 -> split bf16 into R0/R1 (stride 136)
    __nv_bfloat16* H0h = R0;
    __nv_bfloat16* H0l = R1;
    #pragma unroll
    for (int mt = 0; mt < 2; ++mt) {
        const int m0 = mb + mt * 16 + g;
        #pragma unroll
        for (int nt = 0; nt < 8; ++nt) {
            const int col = nb + nt * 8 + 2 * tg;
            const float bb0 = __ldg(bA + col), bb1 = __ldg(bA + col + 1);
            store_split_pair(H0h, H0l, m0,     col,
                             fmaxf(acc[mt][nt][0] + bb0, 0.f),
                             fmaxf(acc[mt][nt][1] + bb1, 0.f));
            store_split_pair(H0h, H0l, m0 + 8, col,
                             fmaxf(acc[mt][nt][2] + bb0, 0.f),
                             fmaxf(acc[mt][nt][3] + bb1, 0.f));
        }
    }
    __syncthreads();

    // ======== Stage 2a: t1 = relu(h0 @ w1^T + b1) ========
    {
        __nv_bfloat16* Wh = R4;  // w1 split, [n][136]
        __nv_bfloat16* Wl = R5;
        #pragma unroll 4
        for (int i = tid; i < 16384; i += 256) {
            const int n = i >> 7, k = i & 127;
            __nv_bfloat16 h, l;
            split_bf16(__ldg(w1 + n * 128 + k), h, l);
            Wh[n * S2ST + k] = h;
            Wl[n * S2ST + k] = l;
        }
        __syncthreads();
        #pragma unroll
        for (int a = 0; a < 2; ++a)
            #pragma unroll
            for (int b = 0; b < 8; ++b)
                #pragma unroll
                for (int c = 0; c < 4; ++c) acc[a][b][c] = 0.f;
        gemm_step<S2ST, S2ST>(H0h, H0l, Wh, Wl, 8, acc, mb, nb, g, tg);

        // t1 -> R2/R3 (old stage-1 B, idle)
        __nv_bfloat16* T1h = R2;
        __nv_bfloat16* T1l = R3;
        #pragma unroll
        for (int mt = 0; mt < 2; ++mt) {
            const int m0 = mb + mt * 16 + g;
            #pragma unroll
            for (int nt = 0; nt < 8; ++nt) {
                const int col = nb + nt * 8 + 2 * tg;
                const float bb0 = __ldg(b1 + col), bb1 = __ldg(b1 + col + 1);
                store_split_pair(T1h, T1l, m0,     col,
                                 fmaxf(acc[mt][nt][0] + bb0, 0.f),
                                 fmaxf(acc[mt][nt][1] + bb1, 0.f));
                store_split_pair(T1h, T1l, m0 + 8, col,
                                 fmaxf(acc[mt][nt][2] + bb0, 0.f),
                                 fmaxf(acc[mt][nt][3] + bb1, 0.f));
            }
        }
        __syncthreads();
    }

    // ======== Stage 2b: h1 = relu(h0 + t1 @ w2^T + b2) -> fp32 F1 ========
    float* F1 = (float*)(smem + 2 * REGB);  // [128][133] fp32, overlays R2/R3
    {
        __nv_bfloat16* Wh = R4;  // w2 split (reuse)
        __nv_bfloat16* Wl = R5;
        #pragma unroll 4
        for (int i = tid; i < 16384; i += 256) {
            const int n = i >> 7, k = i & 127;
            __nv_bfloat16 h, l;
            split_bf16(__ldg(w2 + n * 128 + k), h, l);
            Wh[n * S2ST + k] = h;
            Wl[n * S2ST + k] = l;
        }
        __syncthreads();
        #pragma unroll
        for (int a = 0; a < 2; ++a)
            #pragma unroll
            for (int b = 0; b < 8; ++b)
                #pragma unroll
                for (int c = 0; c < 4; ++c) acc[a][b][c] = 0.f;
        __nv_bfloat16* T1h = R2;
        __nv_bfloat16* T1l = R3;
        gemm_step<S2ST, S2ST>(T1h, T1l, Wh, Wl, 8, acc, mb, nb, g, tg);
        __syncthreads();  // all T1 reads done before F1 overlays R2/R3

        #pragma unroll
        for (int mt = 0; mt < 2; ++mt) {
            const int m0 = mb + mt * 16 + g;
            #pragma unroll
            for (int nt = 0; nt < 8; ++nt) {
                const int col = nb + nt * 8 + 2 * tg;
                const float bb0 = __ldg(b2 + col), bb1 = __ldg(b2 + col + 1);
                const float h00 = __bfloat162float(H0h[m0 * S2ST + col])
                                + __bfloat162float(H0l[m0 * S2ST + col]);
                const float h01 = __bfloat162float(H0h[m0 * S2ST + col + 1])
                                + __bfloat162float(H0l[m0 * S2ST + col + 1]);
                const float h10 = __bfloat162float(H0h[(m0 + 8) * S2ST + col])
                                + __bfloat162float(H0l[(m0 + 8) * S2ST + col]);
                const float h11 = __bfloat162float(H0h[(m0 + 8) * S2ST + col + 1])
                                + __bfloat162float(H0l[(m0 + 8) * S2ST + col + 1]);
                F1[m0 * F1ST + col]           = fmaxf(h00 + acc[mt][nt][0] + bb0, 0.f);
                F1[m0 * F1ST + col + 1]       = fmaxf(h01 + acc[mt][nt][1] + bb1, 0.f);
                F1[(m0 + 8) * F1ST + col]     = fmaxf(h10 + acc[mt][nt][2] + bb0, 0.f);
                F1[(m0 + 8) * F1ST + col + 1] = fmaxf(h11 + acc[mt][nt][3] + bb1, 0.f);
            }
        }
    }

    // load wB transposed: wBs[k][36] (n-contiguous) into R4 region
    float* wBs = (float*)(smem + 4 * REGB);
    for (int i = tid; i < 4096; i += 256) {
        const int n = i & 31, k = i >> 5;
        wBs[k * 36 + n] = __ldg(wB + n * 128 + k);
    }
    __syncthreads();

    // ======== Stage 3: h2 = relu(h1 @ wB^T + bB) (fp32 scalar) ========
    float* F2 = (float*)(smem + 5 * REGB);  // [128][36] fp32
    {
        const int r  = tid >> 1;
        const int n0 = (tid & 1) * 16;
        float a3[16];
        #pragma unroll
        for (int i = 0; i < 16; ++i) a3[i] = 0.f;
        #pragma unroll 2
        for (int k = 0; k < 128; ++k) {
            const float hv = F1[r * F1ST + k];
            const float4* wp = (const float4*)(wBs + k * 36 + n0);
            const float4 q0 = wp[0], q1 = wp[1], q2 = wp[2], q3 = wp[3];
            a3[0]  = fmaf(hv, q0.x, a3[0]);  a3[1]  = fmaf(hv, q0.y, a3[1]);
            a3[2]  = fmaf(hv, q0.z, a3[2]);  a3[3]  = fmaf(hv, q0.w, a3[3]);
            a3[4]  = fmaf(hv, q1.x, a3[4]);  a3[5]  = fmaf(hv, q1.y, a3[5]);
            a3[6]  = fmaf(hv, q1.z, a3[6]);  a3[7]  = fmaf(hv, q1.w, a3[7]);
            a3[8]  = fmaf(hv, q2.x, a3[8]);  a3[9]  = fmaf(hv, q2.y, a3[9]);
            a3[10] = fmaf(hv, q2.z, a3[10]); a3[11] = fmaf(hv, q2.w, a3[11]);
            a3[12] = fmaf(hv, q3.x, a3[12]); a3[13] = fmaf(hv, q3.y, a3[13]);
            a3[14] = fmaf(hv, q3.z, a3[14]); a3[15] = fmaf(hv, q3.w, a3[15]);
        }
        #pragma unroll
        for (int n = 0; n < 16; ++n)
            F2[r * 36 + n0 + n] = fmaxf(a3[n] + __ldg(bB + n0 + n), 0.f);
    }
    __syncthreads();

    // ======== Stage 4: logits = h2 @ wC^T + bC ========
    {
        const int r = tid >> 1;
        const int c = tid & 1;
        float s = __ldg(bC + c);
        #pragma unroll
        for (int k = 0; k < 32; ++k)
            s = fmaf(F2[r * 36 + k], __ldg(wC + c * 32 + k), s);
        out[(size_t)(row0 + r) * 2 + c] = s;
    }
}

// ---------------- launch ----------------
extern "C" void kernel_launch(void* const* d_in, const int* in_sizes, int n_in,
                              void* d_out, int out_size)
{
    const float* x      = (const float*)d_in[0];
    const float* w_step = (const float*)d_in[1];
    const float* b_step = (const float*)d_in[2];
    const float* wA     = (const float*)d_in[3];
    const float* bA     = (const float*)d_in[4];
    const float* w1     = (const float*)d_in[5];
    const float* b1     = (const float*)d_in[6];
    const float* w2     = (const float*)d_in[7];
    const float* b2     = (const float*)d_in[8];
    const float* wB     = (const float*)d_in[9];
    const float* bB     = (const float*)d_in[10];
    const float* wC     = (const float*)d_in[11];
    const float* bC     = (const float*)d_in[12];
    float* out          = (float*)d_out;

    cudaFuncSetAttribute(mlp_kernel, cudaFuncAttributeMaxDynamicSharedMemorySize, SMEM_BYTES);

    feat_kernel<<<BATCH, 256>>>(x, w_step, b_step);
    mlp_kernel<<<BATCH / 128, 256, SMEM_BYTES>>>(wA, bA, w1, b1, w2, b2,
                                                 wB, bB, wC, bC, out);
}